// round 15
// baseline (speedup 1.0000x reference)
#include <cuda_runtime.h>

// SimpleLSTM fused persistent kernel, v5.
// B=64, T=2048, I=H=512. 128 CTAs x 512 threads (16 warps/SM); CTA owns 4
// hidden columns (16 gate rows). Weights staged in smem once (XOR-swizzled,
// same layout as v4). h exchanged via global double buffer + flag-array grid
// barrier; early-arrive with x-projection of t+1 between arrive and wait.
// v5: 2 batches/thread (half per-thread work, double warps for latency
// cover), 16-shfl transposing reduction, store-splitting lane pairs, bias
// applied post-reduction.
//
// Lane map (lane = tid&31): rh = lane>>4 (column pair: cols 2rh,2rh+1),
// bp = (lane>>3)&1 (batch pair), ks = lane&7 (k-split). warp = bg (batch
// group 0..15), thread batches bg*4+bp*2+{0,1}. Within ks: ci = ks>>2
// (output column), gh = (ks>>1)&1 (gate half), bi = ks&1 (output batch).

#define BB 64
#define TT 2048
#define II 512
#define HH 512
#define NCTA 128
#define NTHR 512

__device__ __align__(16) float g_hbuf[2][BB * HH]; // [buf][b*HH + col]
__device__ unsigned g_flags[NCTA];                 // monotone per-CTA epochs

__device__ __forceinline__ float tanh_fast(float x) {
    float y;
    asm("tanh.approx.f32 %0, %1;" : "=f"(y) : "f"(x));
    return y;
}
__device__ __forceinline__ float sig_fast(float x) {
    return fmaf(0.5f, tanh_fast(0.5f * x), 0.5f);
}

__device__ __forceinline__ unsigned long long fma2(
    unsigned long long a, unsigned long long b, unsigned long long c) {
    unsigned long long d;
    asm("fma.rn.f32x2 %0, %1, %2, %3;" : "=l"(d) : "l"(a), "l"(b), "l"(c));
    return d;
}
__device__ __forceinline__ unsigned long long pack2(float lo, float hi) {
    unsigned long long r;
    asm("mov.b64 %0, {%1, %2};" : "=l"(r) : "f"(lo), "f"(hi));
    return r;
}
__device__ __forceinline__ void unpack2(unsigned long long p, float& lo, float& hi) {
    asm("mov.b64 {%0, %1}, %2;" : "=f"(lo), "=f"(hi) : "l"(p));
}

// One K=512 matvec phase, packed over k-parity, 2 batches.
// pk[16]: index (g*2 + c2)*2 + b; each holds (even-k sum, odd-k sum).
// Weight smem: float4 slot (kp, rp), rp = g*2 + ch (column pair ch), content
//   (W[g][2ch][2kp], W[g][2ch][2kp+1], W[g][2ch+1][2kp], W[g][2ch+1][2kp+1])
// at phys = kp*8 + (rp ^ ((kp>>1)&7)). Thread touches kp = 16q + 2ks + p,
// so (kp>>1)&7 == ks (uniform per thread).
template <bool CG>
__device__ __forceinline__ void mvphase(
    unsigned long long* pk,
    const float* p0, const float* p1,
    const float4* __restrict__ W, int ks, int rh)
{
    const int tb = 16 * ks;       // float4-slot base for q=0, p=0
    const int o0 = (0 + rh) ^ ks; // (g*2+rh)^ks per gate
    const int o1 = (2 + rh) ^ ks;
    const int o2 = (4 + rh) ^ ks;
    const int o3 = (6 + rh) ^ ks;

    float4 c0, c1;
    {
        const int k0 = ks * 4;
        if (CG) {
            c0 = __ldcg((const float4*)(p0 + k0));
            c1 = __ldcg((const float4*)(p1 + k0));
        } else {
            c0 = *(const float4*)(p0 + k0);
            c1 = *(const float4*)(p1 + k0);
        }
    }
#pragma unroll 4
    for (int q = 0; q < 16; q++) {
        float4 n0, n1;
        if (q < 15) {
            const int kn = ((q + 1) * 8 + ks) * 4;
            if (CG) {
                n0 = __ldcg((const float4*)(p0 + kn));
                n1 = __ldcg((const float4*)(p1 + kn));
            } else {
                n0 = *(const float4*)(p0 + kn);
                n1 = *(const float4*)(p1 + kn);
            }
        }
        const int qb = 128 * q + tb;
        const unsigned long long aL0 = pack2(c0.x, c0.y), aH0 = pack2(c0.z, c0.w);
        const unsigned long long aL1 = pack2(c1.x, c1.y), aH1 = pack2(c1.z, c1.w);
#pragma unroll
        for (int g = 0; g < 4; g++) {
            const int off = (g == 0) ? o0 : (g == 1) ? o1 : (g == 2) ? o2 : o3;
            unsigned long long* aP = &pk[g * 4]; // (g*2+c2)*2+b, c2,b in {0,1}
            { // p = 0 (even k-pair)
                float4 w4 = W[qb + off];
                unsigned long long wA = pack2(w4.x, w4.y); // col 2rh
                unsigned long long wB = pack2(w4.z, w4.w); // col 2rh+1
                aP[0] = fma2(wA, aL0, aP[0]);
                aP[1] = fma2(wA, aL1, aP[1]);
                aP[2] = fma2(wB, aL0, aP[2]);
                aP[3] = fma2(wB, aL1, aP[3]);
            }
            { // p = 1 (odd k-pair)
                float4 w4 = W[qb + 8 + off];
                unsigned long long wA = pack2(w4.x, w4.y);
                unsigned long long wB = pack2(w4.z, w4.w);
                aP[0] = fma2(wA, aH0, aP[0]);
                aP[1] = fma2(wA, aH1, aP[1]);
                aP[2] = fma2(wB, aH0, aP[2]);
                aP[3] = fma2(wB, aH1, aP[3]);
            }
        }
        if (q < 15) { c0 = n0; c1 = n1; }
    }
}

__global__ void __launch_bounds__(NTHR, 1) lstm_persistent(
    const float* __restrict__ x,   // [B][T][I]
    const float* __restrict__ Wx,  // [4H][I]
    const float* __restrict__ bx,  // [4H]
    const float* __restrict__ Wh,  // [4H][H]
    const float* __restrict__ bh,  // [4H]
    float* __restrict__ out,       // [B][T][H] (+ optional h_n, c_n)
    int write_hn, int write_cn)
{
    extern __shared__ __align__(16) unsigned char smem_raw[];
    float4* W4x = (float4*)(smem_raw);
    float4* W4h = (float4*)(smem_raw + 32768);
    float*  s_bias = (float*)(smem_raw + 65536); // 16 floats [g*4 + col]

    const int tid  = threadIdx.x;
    const int warp = tid >> 5;         // = bg (batch group 0..15)
    const int lane = tid & 31;
    const int rh   = lane >> 4;        // column pair: cols (2rh, 2rh+1)
    const int bp   = (lane >> 3) & 1;  // batch pair within group
    const int ks   = lane & 7;         // k-split lane
    const int ci   = ks >> 2;          // output column within pair
    const int gh   = (ks >> 1) & 1;    // gate half (0:{i,f}, 1:{g,o})
    const int bi   = ks & 1;           // output batch within pair
    const int j0   = blockIdx.x * 4;

    // ---- Stage weight slices (float4 slot (kp, rp), swizzled) ----
    for (int idx = tid; idx < 2048; idx += NTHR) {
        const int kp = idx >> 3, rp = idx & 7;
        const int g = rp >> 1, ch = rp & 1;
        const int phys = kp * 8 + (rp ^ ((kp >> 1) & 7));
        const size_t rA = (size_t)g * HH + j0 + ch * 2; // col 2ch
        const size_t rB = rA + 1;                       // col 2ch+1
        const int k0 = kp * 2;
        float4 vx, vh;
        vx.x = Wx[rA * II + k0];
        vx.y = Wx[rA * II + k0 + 1];
        vx.z = Wx[rB * II + k0];
        vx.w = Wx[rB * II + k0 + 1];
        vh.x = Wh[rA * HH + k0];
        vh.y = Wh[rA * HH + k0 + 1];
        vh.z = Wh[rB * HH + k0];
        vh.w = Wh[rB * HH + k0 + 1];
        W4x[phys] = vx;
        W4h[phys] = vh;
    }
    if (tid < 16) {
        const int g = tid >> 2, c = tid & 3;
        const size_t row = (size_t)g * HH + j0 + c;
        s_bias[g * 4 + c] = bx[row] + bh[row];
    }
    __syncthreads();

    const unsigned base = __ldcg(&g_flags[blockIdx.x]); // equal across CTAs

    // Per-thread bias for (gate, own column), applied post-reduction.
    const int colloc = rh * 2 + ci;
    const float bI = s_bias[0 * 4 + colloc];
    const float bF = s_bias[1 * 4 + colloc];
    const float bG = s_bias[2 * 4 + colloc];
    const float bO = s_bias[3 * 4 + colloc];

    const int b0 = warp * 4 + bp * 2;      // first of this thread's 2 batches
    const float* px0 = x + (size_t)(b0 + 0) * TT * II;
    const float* px1 = x + (size_t)(b0 + 1) * TT * II;
    const int ho0 = (b0 + 0) * HH;
    const int ho1 = (b0 + 1) * HH;

    const int myb   = b0 + bi;
    const int mycol = j0 + colloc;

    unsigned long long pk[16];
    auto initacc = [&]() {
#pragma unroll
        for (int i = 0; i < 16; i++) pk[i] = 0ULL;
    };

    float myc = 0.0f, myh = 0.0f;

    // x projection for t=0 (h-independent; no barrier needed yet).
    initacc();
    mvphase<false>(pk, px0, px1, W4x, ks, rh);

    for (int t = 0; t < TT; t++) {
        if (t) {
            const float* hb = g_hbuf[t & 1];
            mvphase<true>(pk, hb + ho0, hb + ho1, W4h, ks, rh);
        }

        // ---- Fold k-parity, then transposing shfl reduction ----
        float s[16];
#pragma unroll
        for (int i = 0; i < 16; i++) {
            float lo, hi;
            unpack2(pk[i], lo, hi);
            s[i] = lo + hi;
        }
        // Stage A (xor 4): resolve column within pair -> v[g*2 + b].
        float v[8];
#pragma unroll
        for (int g = 0; g < 4; g++) {
#pragma unroll
            for (int b = 0; b < 2; b++) {
                const float m0 = s[(g * 2 + 0) * 2 + b];
                const float m1 = s[(g * 2 + 1) * 2 + b];
                const float mine = ci ? m1 : m0;
                const float send = ci ? m0 : m1;
                v[g * 2 + b] = mine + __shfl_xor_sync(0xffffffffu, send, 4);
            }
        }
        // Stage B (xor 1): resolve batch within pair -> w[g].
        float w[4];
#pragma unroll
        for (int g = 0; g < 4; g++) {
            const float a = v[g * 2 + 0];
            const float b = v[g * 2 + 1];
            const float mine = bi ? b : a;
            const float send = bi ? a : b;
            w[g] = mine + __shfl_xor_sync(0xffffffffu, send, 1);
        }
        // Stage C (xor 2): reduce, keeping this lane's gate half.
        float kept[2];
#pragma unroll
        for (int j = 0; j < 2; j++) {
            const float mine = gh ? w[2 + j] : w[j];
            const float send = gh ? w[j] : w[2 + j];
            kept[j] = mine + __shfl_xor_sync(0xffffffffu, send, 2);
        }
        // Gather (xor 2): fetch partner's completed gate half.
        float other[2];
#pragma unroll
        for (int j = 0; j < 2; j++)
            other[j] = __shfl_xor_sync(0xffffffffu, kept[j], 2);

        const float si = (gh ? other[0] : kept[0]) + bI;
        const float sf = (gh ? other[1] : kept[1]) + bF;
        const float sg = (gh ? kept[0] : other[0]) + bG;
        const float so = (gh ? kept[1] : other[1]) + bO;

        // Pointwise (both lanes of the pair compute identically).
        const float gi = sig_fast(si);
        const float gf = sig_fast(sf);
        const float gg = tanh_fast(sg);
        const float go = sig_fast(so);
        myc = fmaf(gf, myc, gi * gg);
        myh = go * tanh_fast(myc);

        // Store split across the lane pair.
        if (gh == 0)
            out[((size_t)myb * TT + t) * HH + mycol] = myh;
        else
            __stcg(&g_hbuf[(t + 1) & 1][myb * HH + mycol], myh);

        if (t == TT - 1) break;

        // ---- Early arrive (flag array), x-phase of t+1, then wait. ----
        __threadfence();   // publish h stores (gpu scope)
        __syncthreads();   // all threads' fences done
        const unsigned tgt = base + (unsigned)(t + 1);
        if (tid == 0) __stcg(&g_flags[blockIdx.x], tgt);

        initacc();
        px0 += II; px1 += II;
        mvphase<false>(pk, px0, px1, W4x, ks, rh);

        int ok;
        do {
            ok = 1;
            if (tid < NCTA)
                ok = ((int)(__ldcg(&g_flags[tid]) - tgt) >= 0);
        } while (!__syncthreads_and(ok));
        __threadfence(); // acquire: order h loads after flag observation
    }

    const size_t TAIL = (size_t)BB * TT * HH;
    if (gh == 0) {
        if (write_hn) out[TAIL + (size_t)myb * HH + mycol] = myh;
        if (write_cn) out[TAIL + (size_t)BB * HH + (size_t)myb * HH + mycol] = myc;
    }
}

extern "C" void kernel_launch(void* const* d_in, const int* in_sizes, int n_in,
                              void* d_out, int out_size) {
    const float* x  = (const float*)d_in[0];
    const float* Wx = (const float*)d_in[1];
    const float* bx = (const float*)d_in[2];
    const float* Wh = (const float*)d_in[3];
    const float* bh = (const float*)d_in[4];

    const int SMEM_BYTES = 65536 + 128;
    cudaFuncSetAttribute(lstm_persistent,
                         cudaFuncAttributeMaxDynamicSharedMemorySize, SMEM_BYTES);
    cudaFuncSetAttribute(lstm_persistent,
                         cudaFuncAttributePreferredSharedMemoryCarveout, 100);

    const long long TAIL = (long long)BB * TT * HH;
    int whn = ((long long)out_size >= TAIL + (long long)BB * HH) ? 1 : 0;
    int wcn = ((long long)out_size >= TAIL + 2LL * BB * HH) ? 1 : 0;

    lstm_persistent<<<NCTA, NTHR, SMEM_BYTES>>>(x, Wx, bx, Wh, bh,
                                                (float*)d_out, whn, wcn);
}